// round 8
// baseline (speedup 1.0000x reference)
#include <cuda_runtime.h>
#include <math.h>
#include <stdint.h>

#define N_NODES 6000
#define DEG 16
#define N_EDGES 96000
#define D_MODEL 256
#define D_MSG 64
#define D_FF 1024
#define N_LAYERS 3
#define RBF_BINS 256
#define WIN 32

// ---------------- scratch (static device memory; no allocation) ----------------
__device__ float g_x[N_NODES * D_MODEL];
__device__ float g_rhat[N_EDGES * 3];
__device__ float g_xj[N_NODES * D_MSG];
__device__ float g_xi[N_NODES * D_MSG];
__device__ float g_xij[N_EDGES * D_MSG];
__device__ float g_xn[N_NODES * D_MSG];
__device__ float g_h[N_NODES * D_FF];
__device__ float g_partial[256];

// ---------------- packed f32x2 helpers (sm_10x) ----------------
__device__ __forceinline__ uint64_t pk2(float lo, float hi) {
    uint64_t r;
    asm("mov.b64 %0, {%1, %2};" : "=l"(r) : "f"(lo), "f"(hi));
    return r;
}
__device__ __forceinline__ void upk2(float& lo, float& hi, uint64_t v) {
    asm("mov.b64 {%0, %1}, %2;" : "=f"(lo), "=f"(hi) : "l"(v));
}
__device__ __forceinline__ void ffma2(uint64_t& d, uint64_t a, uint64_t b) {
    asm("fma.rn.f32x2 %0, %1, %2, %0;" : "+l"(d) : "l"(a), "l"(b));
}

// ---------------- embedding gather ----------------
__global__ void embed_kernel(const int* __restrict__ an,
                             const float* __restrict__ emb,
                             float* __restrict__ x) {
    int i = blockIdx.x;
    int c = threadIdx.x;
    x[i * D_MODEL + c] = emb[an[i] * D_MODEL + c];
}

// ---------------- rhat (once) ----------------
__global__ void rhat_kernel(const float* __restrict__ r,
                            float* __restrict__ rhat) {
    int e = blockIdx.x * blockDim.x + threadIdx.x;
    if (e >= N_EDGES) return;
    float rx = r[e * 3 + 0], ry = r[e * 3 + 1], rz = r[e * 3 + 2];
    float d = sqrtf(rx * rx + ry * ry + rz * rz);
    rhat[e * 3 + 0] = rx / d;
    rhat[e * 3 + 1] = ry / d;
    rhat[e * 3 + 2] = rz / d;
}

// ---------------- fused windowed-RBF edge kernel -------------------------------
#define EDGE_WPITCH 68
#define EDGE_SMEM_BYTES (256 * EDGE_WPITCH * 4 + 16 * WIN * 4 + 16 * 4 * 3)

__global__ void edge_kernel(const float* __restrict__ r,
                            const int* __restrict__ src,
                            const float* __restrict__ We,     // [64,256]
                            const float* __restrict__ bedge,  // [64]
                            const float* __restrict__ xj,
                            const float* __restrict__ xi,
                            float* __restrict__ xij) {
    extern __shared__ float sm[];
    float* sWt = sm;                        // [256][68] transposed Wedge
    float* sy = sm + 256 * EDGE_WPITCH;     // [16][WIN]
    int* sb0 = (int*)(sy + 16 * WIN);       // [16]
    int* ssrc = sb0 + 16;                   // [16]
    float* sd = (float*)(ssrc + 16);        // [16]

    int t = threadIdx.x;
    for (int idx = t; idx < 64 * 256; idx += 256) {
        int ch = idx >> 8, b = idx & 255;
        sWt[b * EDGE_WPITCH + ch] = We[idx];
    }
    int e_sub = t >> 4;
    int chv = t & 15;
    float4 bed = *(const float4*)&bedge[chv * 4];
    const float inv_step = 255.0f / 8.0f;
    const float step = 8.0f / 255.0f;
    const float gamma = inv_step;

    for (int g = blockIdx.x; g < N_NODES; g += gridDim.x) {
        __syncthreads();
        if (t < 16) {
            int e = g * 16 + t;
            float rx = r[e * 3 + 0], ry = r[e * 3 + 1], rz = r[e * 3 + 2];
            float d = sqrtf(rx * rx + ry * ry + rz * rz);
            int cb = (int)(d * inv_step + 0.5f);
            int b0 = cb - WIN / 2;
            b0 = b0 < 0 ? 0 : (b0 > 256 - WIN ? 256 - WIN : b0);
            sb0[t] = b0;
            sd[t] = d;
            ssrc[t] = src[e];
        }
        __syncthreads();
        {
            float d = sd[e_sub];
            int b0 = sb0[e_sub];
            int jb = chv * 2;
#pragma unroll
            for (int i = 0; i < 2; i++) {
                float tt = d - (float)(b0 + jb + i) * step;
                sy[e_sub * WIN + jb + i] = __expf(-gamma * tt * tt);
            }
        }
        __syncthreads();
        {
            int b0 = sb0[e_sub];
            const float* wp = sWt + (size_t)b0 * EDGE_WPITCH + chv * 4;
            const float* yp = sy + e_sub * WIN;
            float4 acc = bed;
#pragma unroll 16
            for (int j = 0; j < WIN; j++) {
                float yv = yp[j];
                float4 w = *(const float4*)(wp + (size_t)j * EDGE_WPITCH);
                acc.x = fmaf(yv, w.x, acc.x);
                acc.y = fmaf(yv, w.y, acc.y);
                acc.z = fmaf(yv, w.z, acc.z);
                acc.w = fmaf(yv, w.w, acc.w);
            }
            int sidx = ssrc[e_sub];
            float4 aj = *(const float4*)&xj[sidx * 64 + chv * 4];
            float4 ai = *(const float4*)&xi[g * 64 + chv * 4];
            acc.x += aj.x + ai.x;
            acc.y += aj.y + ai.y;
            acc.z += aj.z + ai.z;
            acc.w += aj.w + ai.w;
            *(float4*)&xij[(size_t)(g * 16 + e_sub) * 64 + chv * 4] = acc;
        }
    }
}

// ---------------- SGEMM: C[M,N] = A[M,K] @ B[N,K]^T + bias ---------------------
// 128 threads, 64x64 tile, 8x4 micro-tile as 4 row-pairs (f32x2), K-chunk 32.
// B kept pre-duplicated in smem as packed (b,b) uint64 -> zero packing movs.
// Global loads for next chunk issued before compute (software pipeline).
// EPI 0: +bias   EPI 1: silu(+bias)   EPI 3: dual node-proj (bx selects set)
template <int EPI>
__global__ __launch_bounds__(128)
void gemm64(const float* __restrict__ A,
            const float* __restrict__ B,
            float* __restrict__ C,
            int M, int N, int K,
            const float* __restrict__ bias,
            const float* __restrict__ B2,
            const float* __restrict__ bias2,
            float* __restrict__ C2) {
    __shared__ float As[32][64];
    __shared__ uint64_t Bsd[32][64];       // duplicated (b,b) pairs
    int t = threadIdx.x;
    int n0 = blockIdx.x * 64;
    int m0 = blockIdx.y * 64;
    if (EPI == 3) {
        if (blockIdx.x == 1) { B = B2; bias = bias2; C = C2; }
        n0 = 0;
    }
    int r = t & 63;
    int kb = (t >> 6) * 16;        // which 16-k half this thread loads
    int rg8 = (t >> 4) * 8;        // row group of 8 (4 f32x2 pairs)
    int cg4 = (t & 15) * 4;        // col group of 4

    uint64_t acc2[4][4];
#pragma unroll
    for (int i = 0; i < 4; i++)
#pragma unroll
        for (int j = 0; j < 4; j++) acc2[i][j] = 0ull;

    int rowA = m0 + r;
    bool okA = rowA < M;
    const float* Ap = A + (size_t)(okA ? rowA : (M - 1)) * K + kb;
    const float* Bp = B + (size_t)(n0 + r) * K + kb;

    float4 av[4], bv[4];
#pragma unroll
    for (int i = 0; i < 4; i++) {          // preload chunk 0
        av[i] = okA ? *(const float4*)(Ap + i * 4)
                    : make_float4(0.f, 0.f, 0.f, 0.f);
        bv[i] = *(const float4*)(Bp + i * 4);
    }

    for (int k0 = 0; k0 < K; k0 += 32) {
        __syncthreads();                   // smem free from previous compute
#pragma unroll
        for (int i = 0; i < 4; i++) {
            As[kb + i * 4 + 0][r] = av[i].x;
            As[kb + i * 4 + 1][r] = av[i].y;
            As[kb + i * 4 + 2][r] = av[i].z;
            As[kb + i * 4 + 3][r] = av[i].w;
            Bsd[kb + i * 4 + 0][r] = pk2(bv[i].x, bv[i].x);
            Bsd[kb + i * 4 + 1][r] = pk2(bv[i].y, bv[i].y);
            Bsd[kb + i * 4 + 2][r] = pk2(bv[i].z, bv[i].z);
            Bsd[kb + i * 4 + 3][r] = pk2(bv[i].w, bv[i].w);
        }
        __syncthreads();
        if (k0 + 32 < K) {                 // prefetch next chunk during compute
#pragma unroll
            for (int i = 0; i < 4; i++) {
                av[i] = okA ? *(const float4*)(Ap + k0 + 32 + i * 4)
                            : make_float4(0.f, 0.f, 0.f, 0.f);
                bv[i] = *(const float4*)(Bp + k0 + 32 + i * 4);
            }
        }
#pragma unroll 8
        for (int kk = 0; kk < 32; kk++) {
            float4 a0 = *(const float4*)&As[kk][rg8];
            float4 a1 = *(const float4*)&As[kk][rg8 + 4];
            ulonglong2 bd01 = *(const ulonglong2*)&Bsd[kk][cg4];
            ulonglong2 bd23 = *(const ulonglong2*)&Bsd[kk][cg4 + 2];
            uint64_t ap[4] = {pk2(a0.x, a0.y), pk2(a0.z, a0.w),
                              pk2(a1.x, a1.y), pk2(a1.z, a1.w)};
            uint64_t bd[4] = {bd01.x, bd01.y, bd23.x, bd23.y};
#pragma unroll
            for (int i = 0; i < 4; i++)
#pragma unroll
                for (int j = 0; j < 4; j++)
                    ffma2(acc2[i][j], ap[i], bd[j]);
        }
    }
    __syncthreads();

    float4 b4 = *(const float4*)&bias[n0 + cg4];
    float bb[4] = {b4.x, b4.y, b4.z, b4.w};
#pragma unroll
    for (int i = 0; i < 4; i++) {
        float v0[4], v1[4];
#pragma unroll
        for (int j = 0; j < 4; j++) {
            float lo, hi;
            upk2(lo, hi, acc2[i][j]);
            lo += bb[j];
            hi += bb[j];
            if (EPI == 1) {
                lo = __fdividef(lo, 1.0f + __expf(-lo));
                hi = __fdividef(hi, 1.0f + __expf(-hi));
            }
            v0[j] = lo;
            v1[j] = hi;
        }
        int m = m0 + rg8 + 2 * i;
        if (m < M)
            *(float4*)&C[(size_t)m * N + n0 + cg4] =
                make_float4(v0[0], v0[1], v0[2], v0[3]);
        if (m + 1 < M)
            *(float4*)&C[(size_t)(m + 1) * N + n0 + cg4] =
                make_float4(v1[0], v1[1], v1[2], v1[3]);
    }
}

// ---------------- per-node triplet attention ----------------
__global__ void triplet_kernel(const float* __restrict__ xij,
                               const float* __restrict__ rhat,
                               const float* __restrict__ attn,
                               float* __restrict__ xn) {
    __shared__ float sx[64][17];
    __shared__ float rh[16][3];
    __shared__ float sat[64];
    __shared__ float sl[16][16];
    __shared__ float mq[16], zi[16], wp[16];

    int node = blockIdx.x;
    int t = threadIdx.x;
    const float* xb = xij + (size_t)node * 16 * 64;

    for (int idx = t; idx < 1024; idx += 256) {
        int p = idx >> 6, k = idx & 63;
        sx[k][p] = xb[idx];
    }
    if (t < 48) rh[t / 3][t % 3] = rhat[node * 48 + t];
    if (t < 64) sat[t] = attn[t];
    __syncthreads();

    if (t < 240) {
        int q = t / 15;
        int ps = t % 15;
        int p = ps + (ps >= q ? 1 : 0);
        float c = rh[p][0] * rh[q][0] + rh[p][1] * rh[q][1] + rh[p][2] * rh[q][2];
        c = fminf(fmaxf(c, -1.0f + 1e-6f), 1.0f - 1e-6f);
        float c2 = 2.0f * c;
        float t0 = 1.0f, t1 = c;
        float acc;
        {
            float s = 1.0f + sx[0][p] + sx[0][q];
            float si = __fdividef(s, 1.0f + __expf(-s));
            acc = sat[0] * si;
        }
#pragma unroll
        for (int k = 1; k < 64; k++) {
            float z = t1;
            float s = z + sx[k][p] + sx[k][q];
            float si = __fdividef(s, 1.0f + __expf(-s));
            acc = fmaf(sat[k], si, acc);
            float tn = fmaf(c2, t1, -t0);
            t0 = t1; t1 = tn;
        }
        sl[q][ps] = acc;
    }
    __syncthreads();

    if (t < 16) {
        int q = t;
        float m = -1e30f;
#pragma unroll
        for (int ps = 0; ps < 15; ps++) m = fmaxf(m, sl[q][ps]);
        float z = 0.0f;
#pragma unroll
        for (int ps = 0; ps < 15; ps++) z += __expf(sl[q][ps] - m);
        mq[q] = m;
        zi[q] = __fdividef(1.0f, z);
    }
    __syncthreads();

    if (t < 16) {
        int p = t;
        float w = 0.0f;
#pragma unroll
        for (int q = 0; q < 16; q++) {
            if (q == p) continue;
            int ps = (p < q) ? p : p - 1;
            w += __expf(sl[q][ps] - mq[q]) * zi[q];
        }
        wp[p] = w;
    }
    __syncthreads();

    if (t < 64) {
        int k = t;
        float acc = 0.0f;
#pragma unroll
        for (int p = 0; p < 16; p++) acc = fmaf(wp[p], sx[k][p], acc);
        xn[node * 64 + k] = acc;
    }
}

// ---------------- output head ----------------
__global__ void out_partial_kernel(const float* __restrict__ x,
                                   const float* __restrict__ Wfc,
                                   float* __restrict__ partial) {
    __shared__ float red[256];
    float acc = 0.0f;
    for (int idx = blockIdx.x * 256 + threadIdx.x; idx < N_NODES * D_MODEL;
         idx += 256 * 256)
        acc = fmaf(x[idx], Wfc[idx & 255], acc);
    red[threadIdx.x] = acc;
    __syncthreads();
    for (int s = 128; s > 0; s >>= 1) {
        if (threadIdx.x < s) red[threadIdx.x] += red[threadIdx.x + s];
        __syncthreads();
    }
    if (threadIdx.x == 0) partial[blockIdx.x] = red[0];
}

__global__ void out_final_kernel(const float* __restrict__ partial,
                                 const float* __restrict__ bfc,
                                 float* __restrict__ out) {
    if (threadIdx.x == 0) {
        float s = 0.0f;
        for (int i = 0; i < 256; i++) s += partial[i];
        out[0] = s / (float)N_NODES + bfc[0];
    }
}

// ---------------- launcher ----------------
extern "C" void kernel_launch(void* const* d_in, const int* in_sizes, int n_in,
                              void* d_out, int out_size) {
    const float* r     = (const float*)d_in[0];
    const int*   an    = (const int*)d_in[1];
    const int*   src   = (const int*)d_in[2];
    const float* emb   = (const float*)d_in[6];
    const float* Wsrc  = (const float*)d_in[7];
    const float* bsrc  = (const float*)d_in[8];
    const float* Wdst  = (const float*)d_in[9];
    const float* bdst  = (const float*)d_in[10];
    const float* Wedge = (const float*)d_in[11];
    const float* bedge = (const float*)d_in[12];
    const float* attn  = (const float*)d_in[13];
    const float* W1    = (const float*)d_in[14];
    const float* b1    = (const float*)d_in[15];
    const float* W2    = (const float*)d_in[16];
    const float* b2    = (const float*)d_in[17];
    const float* Wfc   = (const float*)d_in[18];
    const float* bfc   = (const float*)d_in[19];
    float* out = (float*)d_out;

    float *x, *rhat, *xj, *xi, *xij, *xn, *h, *part;
    cudaGetSymbolAddress((void**)&x,    g_x);
    cudaGetSymbolAddress((void**)&rhat, g_rhat);
    cudaGetSymbolAddress((void**)&xj,   g_xj);
    cudaGetSymbolAddress((void**)&xi,   g_xi);
    cudaGetSymbolAddress((void**)&xij,  g_xij);
    cudaGetSymbolAddress((void**)&xn,   g_xn);
    cudaGetSymbolAddress((void**)&h,    g_h);
    cudaGetSymbolAddress((void**)&part, g_partial);

    cudaFuncSetAttribute(edge_kernel,
                         cudaFuncAttributeMaxDynamicSharedMemorySize,
                         EDGE_SMEM_BYTES);

    embed_kernel<<<N_NODES, 256>>>(an, emb, x);
    rhat_kernel<<<(N_EDGES + 255) / 256, 256>>>(r, rhat);

    const int MB_NODE = (N_NODES + 63) / 64;   // 94

    for (int l = 0; l < N_LAYERS; l++) {
        gemm64<3><<<dim3(2, MB_NODE), 128>>>(
            x, Wsrc + l * 64 * 256, xj, N_NODES, 64, 256, bsrc + l * 64,
            Wdst + l * 64 * 256, bdst + l * 64, xi);
        edge_kernel<<<444, 256, EDGE_SMEM_BYTES>>>(
            r, src, Wedge + l * 64 * 256, bedge + l * 64, xj, xi, xij);
        triplet_kernel<<<N_NODES, 256>>>(xij, rhat, attn + l * 64, xn);
        gemm64<1><<<dim3(16, MB_NODE), 128>>>(
            xn, W1 + l * D_FF * 64, h, N_NODES, D_FF, 64, b1 + l * D_FF,
            nullptr, nullptr, nullptr);
        gemm64<0><<<dim3(4, MB_NODE), 128>>>(
            h, W2 + l * D_MODEL * D_FF, x, N_NODES, D_MODEL, D_FF,
            b2 + l * D_MODEL, nullptr, nullptr, nullptr);
    }

    out_partial_kernel<<<256, 256>>>(x, Wfc, part);
    out_final_kernel<<<1, 32>>>(part, bfc, out);
}

// round 9
// speedup vs baseline: 1.4190x; 1.4190x over previous
#include <cuda_runtime.h>
#include <math.h>
#include <stdint.h>

#define N_NODES 6000
#define DEG 16
#define N_EDGES 96000
#define D_MODEL 256
#define D_MSG 64
#define D_FF 1024
#define N_LAYERS 3
#define RBF_BINS 256
#define WIN 32

// ---------------- scratch (static device memory; no allocation) ----------------
__device__ float g_x[N_NODES * D_MODEL];
__device__ float g_rhat[N_EDGES * 3];
__device__ float g_xj[N_NODES * D_MSG];
__device__ float g_xi[N_NODES * D_MSG];
__device__ float g_xij[N_EDGES * D_MSG];
__device__ float g_xn[N_NODES * D_MSG];
__device__ float g_h[N_NODES * D_FF];
__device__ float g_partial[256];

// ---------------- packed f32x2 helpers (sm_10x) ----------------
__device__ __forceinline__ uint64_t pk2(float lo, float hi) {
    uint64_t r;
    asm("mov.b64 %0, {%1, %2};" : "=l"(r) : "f"(lo), "f"(hi));
    return r;
}
__device__ __forceinline__ void upk2(float& lo, float& hi, uint64_t v) {
    asm("mov.b64 {%0, %1}, %2;" : "=f"(lo), "=f"(hi) : "l"(v));
}
__device__ __forceinline__ void ffma2(uint64_t& d, uint64_t a, uint64_t b) {
    asm("fma.rn.f32x2 %0, %1, %2, %0;" : "+l"(d) : "l"(a), "l"(b));
}

// ---------------- embedding gather ----------------
__global__ void embed_kernel(const int* __restrict__ an,
                             const float* __restrict__ emb,
                             float* __restrict__ x) {
    int i = blockIdx.x;
    int c = threadIdx.x;
    x[i * D_MODEL + c] = emb[an[i] * D_MODEL + c];
}

// ---------------- rhat (once) ----------------
__global__ void rhat_kernel(const float* __restrict__ r,
                            float* __restrict__ rhat) {
    int e = blockIdx.x * blockDim.x + threadIdx.x;
    if (e >= N_EDGES) return;
    float rx = r[e * 3 + 0], ry = r[e * 3 + 1], rz = r[e * 3 + 2];
    float d = sqrtf(rx * rx + ry * ry + rz * rz);
    rhat[e * 3 + 0] = rx / d;
    rhat[e * 3 + 1] = ry / d;
    rhat[e * 3 + 2] = rz / d;
}

// ---------------- fused windowed-RBF edge kernel -------------------------------
#define EDGE_WPITCH 68
#define EDGE_SMEM_BYTES (256 * EDGE_WPITCH * 4 + 16 * WIN * 4 + 16 * 4 * 3)

__global__ void edge_kernel(const float* __restrict__ r,
                            const int* __restrict__ src,
                            const float* __restrict__ We,     // [64,256]
                            const float* __restrict__ bedge,  // [64]
                            const float* __restrict__ xj,
                            const float* __restrict__ xi,
                            float* __restrict__ xij) {
    extern __shared__ float sm[];
    float* sWt = sm;                        // [256][68] transposed Wedge
    float* sy = sm + 256 * EDGE_WPITCH;     // [16][WIN]
    int* sb0 = (int*)(sy + 16 * WIN);       // [16]
    int* ssrc = sb0 + 16;                   // [16]
    float* sd = (float*)(ssrc + 16);        // [16]

    int t = threadIdx.x;
    for (int idx = t; idx < 64 * 256; idx += 256) {
        int ch = idx >> 8, b = idx & 255;
        sWt[b * EDGE_WPITCH + ch] = We[idx];
    }
    int e_sub = t >> 4;
    int chv = t & 15;
    float4 bed = *(const float4*)&bedge[chv * 4];
    const float inv_step = 255.0f / 8.0f;
    const float step = 8.0f / 255.0f;
    const float gamma = inv_step;

    for (int g = blockIdx.x; g < N_NODES; g += gridDim.x) {
        __syncthreads();
        if (t < 16) {
            int e = g * 16 + t;
            float rx = r[e * 3 + 0], ry = r[e * 3 + 1], rz = r[e * 3 + 2];
            float d = sqrtf(rx * rx + ry * ry + rz * rz);
            int cb = (int)(d * inv_step + 0.5f);
            int b0 = cb - WIN / 2;
            b0 = b0 < 0 ? 0 : (b0 > 256 - WIN ? 256 - WIN : b0);
            sb0[t] = b0;
            sd[t] = d;
            ssrc[t] = src[e];
        }
        __syncthreads();
        {
            float d = sd[e_sub];
            int b0 = sb0[e_sub];
            int jb = chv * 2;
#pragma unroll
            for (int i = 0; i < 2; i++) {
                float tt = d - (float)(b0 + jb + i) * step;
                sy[e_sub * WIN + jb + i] = __expf(-gamma * tt * tt);
            }
        }
        __syncthreads();
        {
            int b0 = sb0[e_sub];
            const float* wp = sWt + (size_t)b0 * EDGE_WPITCH + chv * 4;
            const float* yp = sy + e_sub * WIN;
            float4 acc = bed;
#pragma unroll 16
            for (int j = 0; j < WIN; j++) {
                float yv = yp[j];
                float4 w = *(const float4*)(wp + (size_t)j * EDGE_WPITCH);
                acc.x = fmaf(yv, w.x, acc.x);
                acc.y = fmaf(yv, w.y, acc.y);
                acc.z = fmaf(yv, w.z, acc.z);
                acc.w = fmaf(yv, w.w, acc.w);
            }
            int sidx = ssrc[e_sub];
            float4 aj = *(const float4*)&xj[sidx * 64 + chv * 4];
            float4 ai = *(const float4*)&xi[g * 64 + chv * 4];
            acc.x += aj.x + ai.x;
            acc.y += aj.y + ai.y;
            acc.z += aj.z + ai.z;
            acc.w += aj.w + ai.w;
            *(float4*)&xij[(size_t)(g * 16 + e_sub) * 64 + chv * 4] = acc;
        }
    }
}

// ---------------- SGEMM: C[M,N] = A[M,K] @ B[N,K]^T + bias ---------------------
// (R7 version: 128 threads, 64x64 tile, 8x4 micro-tile as f32x2 row-pairs.)
template <int EPI>
__global__ __launch_bounds__(128)
void gemm64(const float* __restrict__ A,
            const float* __restrict__ B,
            float* __restrict__ C,
            int M, int N, int K,
            const float* __restrict__ bias,
            const float* __restrict__ B2,
            const float* __restrict__ bias2,
            float* __restrict__ C2) {
    __shared__ float As[32][64];
    __shared__ float Bs[32][64];
    int t = threadIdx.x;
    int n0 = blockIdx.x * 64;
    int m0 = blockIdx.y * 64;
    if (EPI == 3) {
        if (blockIdx.x == 1) { B = B2; bias = bias2; C = C2; }
        n0 = 0;
    }
    int r = t & 63;
    int kb = (t >> 6) * 16;
    int rg8 = (t >> 4) * 8;
    int cg4 = (t & 15) * 4;

    uint64_t acc2[4][4];
#pragma unroll
    for (int i = 0; i < 4; i++)
#pragma unroll
        for (int j = 0; j < 4; j++) acc2[i][j] = 0ull;

    int rowA = m0 + r;
    bool okA = rowA < M;
    const float* Ap = A + (size_t)(okA ? rowA : (M - 1)) * K + kb;
    const float* Bp = B + (size_t)(n0 + r) * K + kb;

    for (int k0 = 0; k0 < K; k0 += 32) {
        float4 av[4], bv[4];
#pragma unroll
        for (int i = 0; i < 4; i++) {
            av[i] = okA ? *(const float4*)(Ap + k0 + i * 4)
                        : make_float4(0.f, 0.f, 0.f, 0.f);
            bv[i] = *(const float4*)(Bp + k0 + i * 4);
        }
        __syncthreads();
#pragma unroll
        for (int i = 0; i < 4; i++) {
            As[kb + i * 4 + 0][r] = av[i].x;
            As[kb + i * 4 + 1][r] = av[i].y;
            As[kb + i * 4 + 2][r] = av[i].z;
            As[kb + i * 4 + 3][r] = av[i].w;
            Bs[kb + i * 4 + 0][r] = bv[i].x;
            Bs[kb + i * 4 + 1][r] = bv[i].y;
            Bs[kb + i * 4 + 2][r] = bv[i].z;
            Bs[kb + i * 4 + 3][r] = bv[i].w;
        }
        __syncthreads();
#pragma unroll 8
        for (int kk = 0; kk < 32; kk++) {
            float4 a0 = *(const float4*)&As[kk][rg8];
            float4 a1 = *(const float4*)&As[kk][rg8 + 4];
            float4 b = *(const float4*)&Bs[kk][cg4];
            uint64_t ap[4] = {pk2(a0.x, a0.y), pk2(a0.z, a0.w),
                              pk2(a1.x, a1.y), pk2(a1.z, a1.w)};
            uint64_t bd[4] = {pk2(b.x, b.x), pk2(b.y, b.y),
                              pk2(b.z, b.z), pk2(b.w, b.w)};
#pragma unroll
            for (int i = 0; i < 4; i++)
#pragma unroll
                for (int j = 0; j < 4; j++)
                    ffma2(acc2[i][j], ap[i], bd[j]);
        }
    }
    __syncthreads();

    float4 b4 = *(const float4*)&bias[n0 + cg4];
    float bb[4] = {b4.x, b4.y, b4.z, b4.w};
#pragma unroll
    for (int i = 0; i < 4; i++) {
        float v0[4], v1[4];
#pragma unroll
        for (int j = 0; j < 4; j++) {
            float lo, hi;
            upk2(lo, hi, acc2[i][j]);
            lo += bb[j];
            hi += bb[j];
            if (EPI == 1) {
                lo = __fdividef(lo, 1.0f + __expf(-lo));
                hi = __fdividef(hi, 1.0f + __expf(-hi));
            }
            v0[j] = lo;
            v1[j] = hi;
        }
        int m = m0 + rg8 + 2 * i;
        if (m < M)
            *(float4*)&C[(size_t)m * N + n0 + cg4] =
                make_float4(v0[0], v0[1], v0[2], v0[3]);
        if (m + 1 < M)
            *(float4*)&C[(size_t)(m + 1) * N + n0 + cg4] =
                make_float4(v1[0], v1[1], v1[2], v1[3]);
    }
}

// ---------------- per-node triplet attention (symmetric-pair version) ----------
// logit(p,q) is symmetric in (p,q): silu arg = T_k(cos) + xij_p + xij_q.
// Compute only the 120 unordered pairs; write both sl[q][p] and sl[p][q-1].
__global__ void triplet_kernel(const float* __restrict__ xij,
                               const float* __restrict__ rhat,
                               const float* __restrict__ attn,
                               float* __restrict__ xn) {
    __shared__ float sx[64][17];
    __shared__ float rh[16][3];
    __shared__ float sat[64];
    __shared__ float sl[16][16];   // [q][p-slot] logits (ps = p<q ? p : p-1)
    __shared__ float mq[16], zi[16], wp[16];

    int node = blockIdx.x;
    int t = threadIdx.x;
    const float* xb = xij + (size_t)node * 16 * 64;

    for (int idx = t; idx < 1024; idx += 256) {
        int p = idx >> 6, k = idx & 63;
        sx[k][p] = xb[idx];
    }
    if (t < 48) rh[t / 3][t % 3] = rhat[node * 48 + t];
    if (t < 64) sat[t] = attn[t];
    __syncthreads();

    if (t < 120) {
        // triangular decode: pair index t -> (p < q)
        int q = (int)((1.0f + sqrtf(8.0f * (float)t + 1.0f)) * 0.5f);
        if (q * (q - 1) / 2 > t) q--;
        else if (q * (q + 1) / 2 <= t) q++;
        int p = t - q * (q - 1) / 2;

        float c = rh[p][0] * rh[q][0] + rh[p][1] * rh[q][1] + rh[p][2] * rh[q][2];
        c = fminf(fmaxf(c, -1.0f + 1e-6f), 1.0f - 1e-6f);
        float c2 = 2.0f * c;
        float t0 = 1.0f, t1 = c;
        float acc;
        {
            float s = 1.0f + sx[0][p] + sx[0][q];
            float si = __fdividef(s, 1.0f + __expf(-s));
            acc = sat[0] * si;
        }
#pragma unroll
        for (int k = 1; k < 64; k++) {
            float z = t1;
            float s = z + sx[k][p] + sx[k][q];
            float si = __fdividef(s, 1.0f + __expf(-s));
            acc = fmaf(sat[k], si, acc);
            float tn = fmaf(c2, t1, -t0);
            t0 = t1; t1 = tn;
        }
        sl[q][p] = acc;        // (p,q): p < q so ps = p
        sl[p][q - 1] = acc;    // (q,p): q > p so ps = q-1
    }
    __syncthreads();

    if (t < 16) {
        int q = t;
        float m = -1e30f;
#pragma unroll
        for (int ps = 0; ps < 15; ps++) m = fmaxf(m, sl[q][ps]);
        float z = 0.0f;
#pragma unroll
        for (int ps = 0; ps < 15; ps++) z += __expf(sl[q][ps] - m);
        mq[q] = m;
        zi[q] = __fdividef(1.0f, z);
    }
    __syncthreads();

    if (t < 16) {
        int p = t;
        float w = 0.0f;
#pragma unroll
        for (int q = 0; q < 16; q++) {
            if (q == p) continue;
            int ps = (p < q) ? p : p - 1;
            w += __expf(sl[q][ps] - mq[q]) * zi[q];
        }
        wp[p] = w;
    }
    __syncthreads();

    if (t < 64) {
        int k = t;
        float acc = 0.0f;
#pragma unroll
        for (int p = 0; p < 16; p++) acc = fmaf(wp[p], sx[k][p], acc);
        xn[node * 64 + k] = acc;
    }
}

// ---------------- output head ----------------
__global__ void out_partial_kernel(const float* __restrict__ x,
                                   const float* __restrict__ Wfc,
                                   float* __restrict__ partial) {
    __shared__ float red[256];
    float acc = 0.0f;
    for (int idx = blockIdx.x * 256 + threadIdx.x; idx < N_NODES * D_MODEL;
         idx += 256 * 256)
        acc = fmaf(x[idx], Wfc[idx & 255], acc);
    red[threadIdx.x] = acc;
    __syncthreads();
    for (int s = 128; s > 0; s >>= 1) {
        if (threadIdx.x < s) red[threadIdx.x] += red[threadIdx.x + s];
        __syncthreads();
    }
    if (threadIdx.x == 0) partial[blockIdx.x] = red[0];
}

__global__ void out_final_kernel(const float* __restrict__ partial,
                                 const float* __restrict__ bfc,
                                 float* __restrict__ out) {
    if (threadIdx.x == 0) {
        float s = 0.0f;
        for (int i = 0; i < 256; i++) s += partial[i];
        out[0] = s / (float)N_NODES + bfc[0];
    }
}

// ---------------- launcher ----------------
extern "C" void kernel_launch(void* const* d_in, const int* in_sizes, int n_in,
                              void* d_out, int out_size) {
    const float* r     = (const float*)d_in[0];
    const int*   an    = (const int*)d_in[1];
    const int*   src   = (const int*)d_in[2];
    const float* emb   = (const float*)d_in[6];
    const float* Wsrc  = (const float*)d_in[7];
    const float* bsrc  = (const float*)d_in[8];
    const float* Wdst  = (const float*)d_in[9];
    const float* bdst  = (const float*)d_in[10];
    const float* Wedge = (const float*)d_in[11];
    const float* bedge = (const float*)d_in[12];
    const float* attn  = (const float*)d_in[13];
    const float* W1    = (const float*)d_in[14];
    const float* b1    = (const float*)d_in[15];
    const float* W2    = (const float*)d_in[16];
    const float* b2    = (const float*)d_in[17];
    const float* Wfc   = (const float*)d_in[18];
    const float* bfc   = (const float*)d_in[19];
    float* out = (float*)d_out;

    float *x, *rhat, *xj, *xi, *xij, *xn, *h, *part;
    cudaGetSymbolAddress((void**)&x,    g_x);
    cudaGetSymbolAddress((void**)&rhat, g_rhat);
    cudaGetSymbolAddress((void**)&xj,   g_xj);
    cudaGetSymbolAddress((void**)&xi,   g_xi);
    cudaGetSymbolAddress((void**)&xij,  g_xij);
    cudaGetSymbolAddress((void**)&xn,   g_xn);
    cudaGetSymbolAddress((void**)&h,    g_h);
    cudaGetSymbolAddress((void**)&part, g_partial);

    cudaFuncSetAttribute(edge_kernel,
                         cudaFuncAttributeMaxDynamicSharedMemorySize,
                         EDGE_SMEM_BYTES);

    embed_kernel<<<N_NODES, 256>>>(an, emb, x);
    rhat_kernel<<<(N_EDGES + 255) / 256, 256>>>(r, rhat);

    const int MB_NODE = (N_NODES + 63) / 64;   // 94

    for (int l = 0; l < N_LAYERS; l++) {
        gemm64<3><<<dim3(2, MB_NODE), 128>>>(
            x, Wsrc + l * 64 * 256, xj, N_NODES, 64, 256, bsrc + l * 64,
            Wdst + l * 64 * 256, bdst + l * 64, xi);
        edge_kernel<<<444, 256, EDGE_SMEM_BYTES>>>(
            r, src, Wedge + l * 64 * 256, bedge + l * 64, xj, xi, xij);
        triplet_kernel<<<N_NODES, 256>>>(xij, rhat, attn + l * 64, xn);
        gemm64<1><<<dim3(16, MB_NODE), 128>>>(
            xn, W1 + l * D_FF * 64, h, N_NODES, D_FF, 64, b1 + l * D_FF,
            nullptr, nullptr, nullptr);
        gemm64<0><<<dim3(4, MB_NODE), 128>>>(
            h, W2 + l * D_MODEL * D_FF, x, N_NODES, D_MODEL, D_FF,
            b2 + l * D_MODEL, nullptr, nullptr, nullptr);
    }

    out_partial_kernel<<<256, 256>>>(x, Wfc, part);
    out_final_kernel<<<1, 32>>>(part, bfc, out);
}

// round 10
// speedup vs baseline: 1.8707x; 1.3183x over previous
#include <cuda_runtime.h>
#include <math.h>
#include <stdint.h>

#define N_NODES 6000
#define DEG 16
#define N_EDGES 96000
#define D_MODEL 256
#define D_MSG 64
#define D_FF 1024
#define N_LAYERS 3
#define RBF_BINS 256
#define WIN 32
#define N_SPEC 108

// ---------------- scratch (static device memory; no allocation) ----------------
__device__ float g_rhat[N_EDGES * 3];
__device__ float g_xj[N_NODES * D_MSG];
__device__ float g_xi[N_NODES * D_MSG];
__device__ float g_xij[N_EDGES * D_MSG];
__device__ float g_xn[N_NODES * D_MSG];
__device__ float g_h[N_NODES * D_FF];
__device__ float g_w2t[2 * D_FF * D_MODEL];      // W2 layer0/1 transposed [1024,256]
__device__ float g_wc[4 * D_MSG * D_FF];         // fused Wsrc@W2 / Wdst@W2 [64,1024]
__device__ float g_embsrc[112 * D_MSG];
__device__ float g_embdst[112 * D_MSG];
__device__ float g_bx[4 * D_MSG];                // fused biases
__device__ float g_hpart[60 * D_FF];
__device__ float g_hsum[D_FF];
__device__ float g_wfc2[D_FF];
__device__ float g_zeros[D_FF];                  // zero-initialized

// ---------------- packed f32x2 helpers (sm_10x) ----------------
__device__ __forceinline__ uint64_t pk2(float lo, float hi) {
    uint64_t r;
    asm("mov.b64 %0, {%1, %2};" : "=l"(r) : "f"(lo), "f"(hi));
    return r;
}
__device__ __forceinline__ void upk2(float& lo, float& hi, uint64_t v) {
    asm("mov.b64 {%0, %1}, %2;" : "=f"(lo), "=f"(hi) : "l"(v));
}
__device__ __forceinline__ void ffma2(uint64_t& d, uint64_t a, uint64_t b) {
    asm("fma.rn.f32x2 %0, %1, %2, %0;" : "+l"(d) : "l"(a), "l"(b));
}

// ---------------- rhat (once) ----------------
__global__ void rhat_kernel(const float* __restrict__ r,
                            float* __restrict__ rhat) {
    int e = blockIdx.x * blockDim.x + threadIdx.x;
    if (e >= N_EDGES) return;
    float rx = r[e * 3 + 0], ry = r[e * 3 + 1], rz = r[e * 3 + 2];
    float d = sqrtf(rx * rx + ry * ry + rz * rz);
    rhat[e * 3 + 0] = rx / d;
    rhat[e * 3 + 1] = ry / d;
    rhat[e * 3 + 2] = rz / d;
}

// ---------------- transpose [R,C] -> [C,R] ----------------
__global__ void transpose_kernel(const float* __restrict__ in,
                                 float* __restrict__ out, int R, int C) {
    __shared__ float tile[32][33];
    int c0 = blockIdx.x * 32, r0 = blockIdx.y * 32;
    int tx = threadIdx.x, ty = threadIdx.y;
#pragma unroll
    for (int i = 0; i < 4; i++)
        tile[ty + i * 8][tx] = in[(size_t)(r0 + ty + i * 8) * C + c0 + tx];
    __syncthreads();
#pragma unroll
    for (int i = 0; i < 4; i++)
        out[(size_t)(c0 + ty + i * 8) * R + r0 + tx] = tile[tx][ty + i * 8];
}

// ---------------- fused bias: bx[c] = bsrc[c] + sum_k Wsrc[c][k]*b2prev[k] ----
__global__ void biasfold_kernel(const float* __restrict__ Wsrc,
                                const float* __restrict__ Wdst,
                                const float* __restrict__ bsrc,
                                const float* __restrict__ bdst,
                                const float* __restrict__ b2,
                                float* __restrict__ bx) {
    // blockIdx.x: 0..3 -> (layer 1 src, layer 1 dst, layer 2 src, layer 2 dst)
    int which = blockIdx.x;
    int l = 1 + (which >> 1);
    bool isdst = which & 1;
    const float* W = (isdst ? Wdst : Wsrc) + (size_t)l * D_MSG * D_MODEL;
    const float* bb = (isdst ? bdst : bsrc) + (size_t)l * D_MSG;
    const float* b2p = b2 + (size_t)(l - 1) * D_MODEL;
    int c = threadIdx.x;
    float acc = bb[c];
    for (int k = 0; k < D_MODEL; k++) acc = fmaf(W[c * D_MODEL + k], b2p[k], acc);
    bx[which * D_MSG + c] = acc;
}

// ---------------- layer-0 projection gather ----------------
__global__ void gather_kernel(const int* __restrict__ an,
                              const float* __restrict__ es,
                              const float* __restrict__ ed,
                              float* __restrict__ xj,
                              float* __restrict__ xi) {
    int i = blockIdx.x;
    int c = threadIdx.x;
    int a = an[i];
    xj[i * D_MSG + c] = es[a * D_MSG + c];
    xi[i * D_MSG + c] = ed[a * D_MSG + c];
}

// ---------------- fused windowed-RBF edge kernel -------------------------------
#define EDGE_WPITCH 68
#define EDGE_SMEM_BYTES (256 * EDGE_WPITCH * 4 + 16 * WIN * 4 + 16 * 4 * 3)

__global__ void edge_kernel(const float* __restrict__ r,
                            const int* __restrict__ src,
                            const float* __restrict__ We,     // [64,256]
                            const float* __restrict__ bedge,  // [64]
                            const float* __restrict__ xj,
                            const float* __restrict__ xi,
                            float* __restrict__ xij) {
    extern __shared__ float sm[];
    float* sWt = sm;
    float* sy = sm + 256 * EDGE_WPITCH;
    int* sb0 = (int*)(sy + 16 * WIN);
    int* ssrc = sb0 + 16;
    float* sd = (float*)(ssrc + 16);

    int t = threadIdx.x;
    for (int idx = t; idx < 64 * 256; idx += 256) {
        int ch = idx >> 8, b = idx & 255;
        sWt[b * EDGE_WPITCH + ch] = We[idx];
    }
    int e_sub = t >> 4;
    int chv = t & 15;
    float4 bed = *(const float4*)&bedge[chv * 4];
    const float inv_step = 255.0f / 8.0f;
    const float step = 8.0f / 255.0f;
    const float gamma = inv_step;

    for (int g = blockIdx.x; g < N_NODES; g += gridDim.x) {
        __syncthreads();
        if (t < 16) {
            int e = g * 16 + t;
            float rx = r[e * 3 + 0], ry = r[e * 3 + 1], rz = r[e * 3 + 2];
            float d = sqrtf(rx * rx + ry * ry + rz * rz);
            int cb = (int)(d * inv_step + 0.5f);
            int b0 = cb - WIN / 2;
            b0 = b0 < 0 ? 0 : (b0 > 256 - WIN ? 256 - WIN : b0);
            sb0[t] = b0;
            sd[t] = d;
            ssrc[t] = src[e];
        }
        __syncthreads();
        {
            float d = sd[e_sub];
            int b0 = sb0[e_sub];
            int jb = chv * 2;
#pragma unroll
            for (int i = 0; i < 2; i++) {
                float tt = d - (float)(b0 + jb + i) * step;
                sy[e_sub * WIN + jb + i] = __expf(-gamma * tt * tt);
            }
        }
        __syncthreads();
        {
            int b0 = sb0[e_sub];
            const float* wp = sWt + (size_t)b0 * EDGE_WPITCH + chv * 4;
            const float* yp = sy + e_sub * WIN;
            float4 acc = bed;
#pragma unroll 16
            for (int j = 0; j < WIN; j++) {
                float yv = yp[j];
                float4 w = *(const float4*)(wp + (size_t)j * EDGE_WPITCH);
                acc.x = fmaf(yv, w.x, acc.x);
                acc.y = fmaf(yv, w.y, acc.y);
                acc.z = fmaf(yv, w.z, acc.z);
                acc.w = fmaf(yv, w.w, acc.w);
            }
            int sidx = ssrc[e_sub];
            float4 aj = *(const float4*)&xj[sidx * 64 + chv * 4];
            float4 ai = *(const float4*)&xi[g * 64 + chv * 4];
            acc.x += aj.x + ai.x;
            acc.y += aj.y + ai.y;
            acc.z += aj.z + ai.z;
            acc.w += aj.w + ai.w;
            *(float4*)&xij[(size_t)(g * 16 + e_sub) * 64 + chv * 4] = acc;
        }
    }
}

// ---------------- SGEMM: C[M,N] = A[M,K] @ B[N,K]^T + bias ---------------------
// 128 threads, 64x64 tile, 8x4 micro-tile as f32x2 row-pairs.
// EPI 0: +bias   EPI 1: silu(+bias)
// EPI 3: dual (blockIdx.x selects B/bias/C; N=64)
// EPI 5: dual-A (blockIdx.y selects A/C; m0=0, shared B and zero bias)
template <int EPI>
__global__ __launch_bounds__(128)
void gemm64(const float* __restrict__ A,
            const float* __restrict__ B,
            float* __restrict__ C,
            int M, int N, int K,
            const float* __restrict__ bias,
            const float* __restrict__ B2,
            const float* __restrict__ bias2,
            float* __restrict__ C2) {
    __shared__ float As[32][64];
    __shared__ float Bs[32][64];
    int t = threadIdx.x;
    int n0 = blockIdx.x * 64;
    int m0 = blockIdx.y * 64;
    if (EPI == 3) {
        if (blockIdx.x == 1) { B = B2; bias = bias2; C = C2; }
        n0 = 0;
    }
    if (EPI == 5) {
        m0 = 0;
        if (blockIdx.y == 1) { A = B2; C = C2; }   // B2 slot carries A2
    }
    int r = t & 63;
    int kb = (t >> 6) * 16;
    int rg8 = (t >> 4) * 8;
    int cg4 = (t & 15) * 4;

    uint64_t acc2[4][4];
#pragma unroll
    for (int i = 0; i < 4; i++)
#pragma unroll
        for (int j = 0; j < 4; j++) acc2[i][j] = 0ull;

    int rowA = m0 + r;
    bool okA = rowA < M;
    const float* Ap = A + (size_t)(okA ? rowA : (M - 1)) * K + kb;
    const float* Bp = B + (size_t)(n0 + r) * K + kb;

    for (int k0 = 0; k0 < K; k0 += 32) {
        float4 av[4], bv[4];
#pragma unroll
        for (int i = 0; i < 4; i++) {
            av[i] = okA ? *(const float4*)(Ap + k0 + i * 4)
                        : make_float4(0.f, 0.f, 0.f, 0.f);
            bv[i] = *(const float4*)(Bp + k0 + i * 4);
        }
        __syncthreads();
#pragma unroll
        for (int i = 0; i < 4; i++) {
            As[kb + i * 4 + 0][r] = av[i].x;
            As[kb + i * 4 + 1][r] = av[i].y;
            As[kb + i * 4 + 2][r] = av[i].z;
            As[kb + i * 4 + 3][r] = av[i].w;
            Bs[kb + i * 4 + 0][r] = bv[i].x;
            Bs[kb + i * 4 + 1][r] = bv[i].y;
            Bs[kb + i * 4 + 2][r] = bv[i].z;
            Bs[kb + i * 4 + 3][r] = bv[i].w;
        }
        __syncthreads();
#pragma unroll 8
        for (int kk = 0; kk < 32; kk++) {
            float4 a0 = *(const float4*)&As[kk][rg8];
            float4 a1 = *(const float4*)&As[kk][rg8 + 4];
            float4 b = *(const float4*)&Bs[kk][cg4];
            uint64_t ap[4] = {pk2(a0.x, a0.y), pk2(a0.z, a0.w),
                              pk2(a1.x, a1.y), pk2(a1.z, a1.w)};
            uint64_t bd[4] = {pk2(b.x, b.x), pk2(b.y, b.y),
                              pk2(b.z, b.z), pk2(b.w, b.w)};
#pragma unroll
            for (int i = 0; i < 4; i++)
#pragma unroll
                for (int j = 0; j < 4; j++)
                    ffma2(acc2[i][j], ap[i], bd[j]);
        }
    }
    __syncthreads();

    float4 b4 = *(const float4*)&bias[n0 + cg4];
    float bb[4] = {b4.x, b4.y, b4.z, b4.w};
#pragma unroll
    for (int i = 0; i < 4; i++) {
        float v0[4], v1[4];
#pragma unroll
        for (int j = 0; j < 4; j++) {
            float lo, hi;
            upk2(lo, hi, acc2[i][j]);
            lo += bb[j];
            hi += bb[j];
            if (EPI == 1) {
                lo = __fdividef(lo, 1.0f + __expf(-lo));
                hi = __fdividef(hi, 1.0f + __expf(-hi));
            }
            v0[j] = lo;
            v1[j] = hi;
        }
        int m = m0 + rg8 + 2 * i;
        if (m < M)
            *(float4*)&C[(size_t)m * N + n0 + cg4] =
                make_float4(v0[0], v0[1], v0[2], v0[3]);
        if (m + 1 < M)
            *(float4*)&C[(size_t)(m + 1) * N + n0 + cg4] =
                make_float4(v1[0], v1[1], v1[2], v1[3]);
    }
}

// ---------------- per-node triplet attention (symmetric pairs) ----------------
__global__ void triplet_kernel(const float* __restrict__ xij,
                               const float* __restrict__ rhat,
                               const float* __restrict__ attn,
                               float* __restrict__ xn) {
    __shared__ float sx[64][17];
    __shared__ float rh[16][3];
    __shared__ float sat[64];
    __shared__ float sl[16][16];
    __shared__ float mq[16], zi[16], wp[16];

    int node = blockIdx.x;
    int t = threadIdx.x;
    const float* xb = xij + (size_t)node * 16 * 64;

    for (int idx = t; idx < 1024; idx += 256) {
        int p = idx >> 6, k = idx & 63;
        sx[k][p] = xb[idx];
    }
    if (t < 48) rh[t / 3][t % 3] = rhat[node * 48 + t];
    if (t < 64) sat[t] = attn[t];
    __syncthreads();

    if (t < 120) {
        int q = (int)((1.0f + sqrtf(8.0f * (float)t + 1.0f)) * 0.5f);
        if (q * (q - 1) / 2 > t) q--;
        else if (q * (q + 1) / 2 <= t) q++;
        int p = t - q * (q - 1) / 2;

        float c = rh[p][0] * rh[q][0] + rh[p][1] * rh[q][1] + rh[p][2] * rh[q][2];
        c = fminf(fmaxf(c, -1.0f + 1e-6f), 1.0f - 1e-6f);
        float c2 = 2.0f * c;
        float t0 = 1.0f, t1 = c;
        float acc;
        {
            float s = 1.0f + sx[0][p] + sx[0][q];
            float si = __fdividef(s, 1.0f + __expf(-s));
            acc = sat[0] * si;
        }
#pragma unroll
        for (int k = 1; k < 64; k++) {
            float z = t1;
            float s = z + sx[k][p] + sx[k][q];
            float si = __fdividef(s, 1.0f + __expf(-s));
            acc = fmaf(sat[k], si, acc);
            float tn = fmaf(c2, t1, -t0);
            t0 = t1; t1 = tn;
        }
        sl[q][p] = acc;
        sl[p][q - 1] = acc;
    }
    __syncthreads();

    if (t < 16) {
        int q = t;
        float m = -1e30f;
#pragma unroll
        for (int ps = 0; ps < 15; ps++) m = fmaxf(m, sl[q][ps]);
        float z = 0.0f;
#pragma unroll
        for (int ps = 0; ps < 15; ps++) z += __expf(sl[q][ps] - m);
        mq[q] = m;
        zi[q] = __fdividef(1.0f, z);
    }
    __syncthreads();

    if (t < 16) {
        int p = t;
        float w = 0.0f;
#pragma unroll
        for (int q = 0; q < 16; q++) {
            if (q == p) continue;
            int ps = (p < q) ? p : p - 1;
            w += __expf(sl[q][ps] - mq[q]) * zi[q];
        }
        wp[p] = w;
    }
    __syncthreads();

    if (t < 64) {
        int k = t;
        float acc = 0.0f;
#pragma unroll
        for (int p = 0; p < 16; p++) acc = fmaf(wp[p], sx[k][p], acc);
        xn[node * 64 + k] = acc;
    }
}

// ---------------- head: column sums of h2 ----------------
__global__ void colsum1_kernel(const float* __restrict__ h,
                               float* __restrict__ hpart) {
    int f = blockIdx.y * 256 + threadIdx.x;
    int n0 = blockIdx.x * 100;
    float acc = 0.0f;
    for (int n = n0; n < n0 + 100; n++) acc += h[(size_t)n * D_FF + f];
    hpart[blockIdx.x * D_FF + f] = acc;
}

__global__ void colsum2_kernel(const float* __restrict__ hpart,
                               float* __restrict__ hsum) {
    int f = blockIdx.x * 256 + threadIdx.x;
    float acc = 0.0f;
    for (int b = 0; b < 60; b++) acc += hpart[b * D_FF + f];
    hsum[f] = acc;
}

// ---------------- head: wfc2[f] = sum_k W2_2[k][f] * Wfc[k] ----------------
__global__ void wfc2_kernel(const float* __restrict__ W2l2,
                            const float* __restrict__ Wfc,
                            float* __restrict__ wfc2) {
    int f = blockIdx.x * 256 + threadIdx.x;
    float acc = 0.0f;
    for (int k = 0; k < D_MODEL; k++)
        acc = fmaf(W2l2[(size_t)k * D_FF + f], Wfc[k], acc);
    wfc2[f] = acc;
}

// ---------------- head: final scalar ----------------
__global__ void final_kernel(const float* __restrict__ hsum,
                             const float* __restrict__ wfc2,
                             const float* __restrict__ b2l2,
                             const float* __restrict__ Wfc,
                             const float* __restrict__ bfc,
                             float* __restrict__ out) {
    __shared__ float red[256];
    int t = threadIdx.x;
    float acc = 0.0f;
    for (int f = t; f < D_FF; f += 256) acc = fmaf(hsum[f], wfc2[f], acc);
    acc *= (1.0f / (float)N_NODES);
    acc = fmaf(b2l2[t], Wfc[t], acc);   // b2 . Wfc contribution (t < 256)
    red[t] = acc;
    __syncthreads();
    for (int s = 128; s > 0; s >>= 1) {
        if (t < s) red[t] += red[t + s];
        __syncthreads();
    }
    if (t == 0) out[0] = red[0] + bfc[0];
}

// ---------------- launcher ----------------
extern "C" void kernel_launch(void* const* d_in, const int* in_sizes, int n_in,
                              void* d_out, int out_size) {
    const float* r     = (const float*)d_in[0];
    const int*   an    = (const int*)d_in[1];
    const int*   src   = (const int*)d_in[2];
    const float* emb   = (const float*)d_in[6];
    const float* Wsrc  = (const float*)d_in[7];
    const float* bsrc  = (const float*)d_in[8];
    const float* Wdst  = (const float*)d_in[9];
    const float* bdst  = (const float*)d_in[10];
    const float* Wedge = (const float*)d_in[11];
    const float* bedge = (const float*)d_in[12];
    const float* attn  = (const float*)d_in[13];
    const float* W1    = (const float*)d_in[14];
    const float* b1    = (const float*)d_in[15];
    const float* W2    = (const float*)d_in[16];
    const float* b2    = (const float*)d_in[17];
    const float* Wfc   = (const float*)d_in[18];
    const float* bfc   = (const float*)d_in[19];
    float* out = (float*)d_out;

    float *rhat, *xj, *xi, *xij, *xn, *h, *w2t, *wc, *es, *ed, *bx;
    float *hpart, *hsum, *wfc2, *zeros;
    cudaGetSymbolAddress((void**)&rhat, g_rhat);
    cudaGetSymbolAddress((void**)&xj,   g_xj);
    cudaGetSymbolAddress((void**)&xi,   g_xi);
    cudaGetSymbolAddress((void**)&xij,  g_xij);
    cudaGetSymbolAddress((void**)&xn,   g_xn);
    cudaGetSymbolAddress((void**)&h,    g_h);
    cudaGetSymbolAddress((void**)&w2t,  g_w2t);
    cudaGetSymbolAddress((void**)&wc,   g_wc);
    cudaGetSymbolAddress((void**)&es,   g_embsrc);
    cudaGetSymbolAddress((void**)&ed,   g_embdst);
    cudaGetSymbolAddress((void**)&bx,   g_bx);
    cudaGetSymbolAddress((void**)&hpart, g_hpart);
    cudaGetSymbolAddress((void**)&hsum, g_hsum);
    cudaGetSymbolAddress((void**)&wfc2, g_wfc2);
    cudaGetSymbolAddress((void**)&zeros, g_zeros);

    cudaFuncSetAttribute(edge_kernel,
                         cudaFuncAttributeMaxDynamicSharedMemorySize,
                         EDGE_SMEM_BYTES);

    // ---------- precompute ----------
    rhat_kernel<<<(N_EDGES + 255) / 256, 256>>>(r, rhat);
    // transpose W2 for layers 0,1
    transpose_kernel<<<dim3(32, 8), dim3(32, 8)>>>(W2, w2t, D_MODEL, D_FF);
    transpose_kernel<<<dim3(32, 8), dim3(32, 8)>>>(
        W2 + D_MODEL * D_FF, w2t + D_FF * D_MODEL, D_MODEL, D_FF);
    // species projections: embsrc/embdst = emb @ Wsrc0^T / Wdst0^T (+bias)
    gemm64<3><<<dim3(2, 2), 128>>>(emb, Wsrc, es, N_SPEC, 64, 256, bsrc,
                                   Wdst, bdst, ed);
    // fused weights: Wc = Wsrc_{l+1} @ W2_l  (as A @ w2t^T), zero bias
    gemm64<5><<<dim3(16, 2), 128>>>(
        Wsrc + 1 * 64 * 256, w2t, wc + 0 * 64 * D_FF, 64, D_FF, 256, zeros,
        Wdst + 1 * 64 * 256, nullptr, wc + 1 * 64 * D_FF);
    gemm64<5><<<dim3(16, 2), 128>>>(
        Wsrc + 2 * 64 * 256, w2t + D_FF * D_MODEL, wc + 2 * 64 * D_FF,
        64, D_FF, 256, zeros,
        Wdst + 2 * 64 * 256, nullptr, wc + 3 * 64 * D_FF);
    // fused biases
    biasfold_kernel<<<4, 64>>>(Wsrc, Wdst, bsrc, bdst, b2, bx);
    // layer-0 projections via species gather
    gather_kernel<<<N_NODES, 64>>>(an, es, ed, xj, xi);

    const int MB_NODE = (N_NODES + 63) / 64;   // 94

    // ---------- layers ----------
    for (int l = 0; l < N_LAYERS; l++) {
        edge_kernel<<<444, 256, EDGE_SMEM_BYTES>>>(
            r, src, Wedge + l * 64 * 256, bedge + l * 64, xj, xi, xij);
        triplet_kernel<<<N_NODES, 256>>>(xij, rhat, attn + l * 64, xn);
        gemm64<1><<<dim3(16, MB_NODE), 128>>>(
            xn, W1 + l * D_FF * 64, h, N_NODES, D_FF, 64, b1 + l * D_FF,
            nullptr, nullptr, nullptr);
        if (l < 2) {
            // next-layer projections fused through FFN2:
            // xj = h @ Wc_src^T + bx_src ; xi = h @ Wc_dst^T + bx_dst
            gemm64<3><<<dim3(2, MB_NODE), 128>>>(
                h, wc + (2 * l + 0) * 64 * D_FF, xj, N_NODES, 64, D_FF,
                bx + (2 * l + 0) * 64,
                wc + (2 * l + 1) * 64 * D_FF, bx + (2 * l + 1) * 64, xi);
        }
    }

    // ---------- head (FFN2 of layer 2 folded into Wfc) ----------
    colsum1_kernel<<<dim3(60, 4), 256>>>(h, hpart);
    colsum2_kernel<<<4, 256>>>(hpart, hsum);
    wfc2_kernel<<<4, 256>>>(W2 + 2 * D_MODEL * D_FF, Wfc, wfc2);
    final_kernel<<<1, 256>>>(hsum, wfc2, b2 + 2 * D_MODEL, Wfc, bfc, out);
}